// round 2
// baseline (speedup 1.0000x reference)
#include <cuda_runtime.h>

// ----------------------------------------------------------------------------
// RadianceRenderer R2: weights via LDG/L1 (no smem staging) -> 3 blocks/SM,
// strided col mapping (4-way instead of 16-way write conflicts),
// padded mini-GEMM for sigma/feat, warp-shuffle scan/reductions.
// Block = 1 ray (64 points), 128 threads.
// ----------------------------------------------------------------------------

#define HID 128
#define STR 68   // padded row stride (floats) for transposed activation tiles

typedef unsigned long long ull;

__device__ __forceinline__ ull pack2(float lo, float hi) {
    ull r;
    asm("mov.b64 %0, {%1, %2};" : "=l"(r)
        : "r"(__float_as_uint(lo)), "r"(__float_as_uint(hi)));
    return r;
}
__device__ __forceinline__ void unpack2(ull v, float& lo, float& hi) {
    unsigned a, b;
    asm("mov.b64 {%0, %1}, %2;" : "=r"(a), "=r"(b) : "l"(v));
    lo = __uint_as_float(a);
    hi = __uint_as_float(b);
}
__device__ __forceinline__ void fma2(ull& d, ull a, ull b) {
    asm("fma.rn.f32x2 %0, %1, %2, %0;" : "+l"(d) : "l"(a), "l"(b));
}

// GEMM tile: 64 points x 128 cols. Weights read from GLOBAL (L1-resident),
// activations (transposed [K][STR]) from smem, broadcast within warp.
// Thread (tx,ty): cols {tx, tx+32, tx+64, tx+96}, points [ty*16, ty*16+16).
template <int K>
__device__ __forceinline__ void gemm_tileG(const float* __restrict__ wg,
                                           const float* __restrict__ a,
                                           int tx, int pb, ull acc[4][8]) {
#pragma unroll 4
    for (int k = 0; k < K; k++) {
        float w0 = __ldg(wg + k * HID + tx);
        float w1 = __ldg(wg + k * HID + tx + 32);
        float w2 = __ldg(wg + k * HID + tx + 64);
        float w3 = __ldg(wg + k * HID + tx + 96);
        ull wp0 = pack2(w0, w0);
        ull wp1 = pack2(w1, w1);
        ull wp2 = pack2(w2, w2);
        ull wp3 = pack2(w3, w3);
        const ulonglong2* hp = (const ulonglong2*)(a + k * STR + pb);
        ulonglong2 u0 = hp[0], u1 = hp[1], u2 = hp[2], u3 = hp[3];
        ull hh[8] = {u0.x, u0.y, u1.x, u1.y, u2.x, u2.y, u3.x, u3.y};
#pragma unroll
        for (int i = 0; i < 8; i++) {
            fma2(acc[0][i], wp0, hh[i]);
            fma2(acc[1][i], wp1, hh[i]);
            fma2(acc[2][i], wp2, hh[i]);
            fma2(acc[3][i], wp3, hh[i]);
        }
    }
}

// Write tile back transposed (dst[col][p]) with bias + relu.
__device__ __forceinline__ void write_tileG(float* __restrict__ dst,
                                            const float* __restrict__ biasg,
                                            int tx, int pb, ull acc[4][8]) {
#pragma unroll
    for (int c = 0; c < 4; c++) {
        int col = tx + 32 * c;
        float bb = __ldg(biasg + col);
        float v[16];
#pragma unroll
        for (int i = 0; i < 8; i++) {
            float lo, hi;
            unpack2(acc[c][i], lo, hi);
            v[2 * i]     = fmaxf(lo + bb, 0.f);
            v[2 * i + 1] = fmaxf(hi + bb, 0.f);
        }
        float4* d = (float4*)(dst + col * STR + pb);
        d[0] = make_float4(v[0], v[1], v[2], v[3]);
        d[1] = make_float4(v[4], v[5], v[6], v[7]);
        d[2] = make_float4(v[8], v[9], v[10], v[11]);
        d[3] = make_float4(v[12], v[13], v[14], v[15]);
    }
}

__global__ __launch_bounds__(128, 3) void radiance_kernel(
    const float* __restrict__ rays_o, const float* __restrict__ rays_d,
    const float* __restrict__ aabb,
    const float* __restrict__ W1, const float* __restrict__ b1,
    const float* __restrict__ W2, const float* __restrict__ b2,
    const float* __restrict__ Wd, const float* __restrict__ bd,
    const float* __restrict__ Wf, const float* __restrict__ bf,
    const float* __restrict__ Wc1, const float* __restrict__ bc1,
    const float* __restrict__ Wc2, const float* __restrict__ bc2,
    float* __restrict__ out) {
    extern __shared__ float sm[];
    float* bufA  = sm;            // 8704  [128][STR]  h1T -> h2T -> hcT
    float* in32  = sm + 8704;     // 2176  [32][STR]: feat rows 0..15, ynm 16..31
    float* sxyz  = sm + 10880;    // 192
    float* sts   = sm + 11072;    // 64
    float* ssig  = sm + 11136;    // 64
    float* sins  = sm + 11200;    // 64
    float* synm  = sm + 11264;    // 16
    float* scol2 = sm + 11280;    // 64
    float* sred  = sm + 11344;    // 16

    const int tid = threadIdx.x;
    const int ray = blockIdx.x;
    const int tx = tid & 31, ty = tid >> 5;
    const int pb = ty * 16;

    // ---- ray setup (all threads, redundant & deterministic) ----
    float ox = rays_o[ray * 3 + 0], oy = rays_o[ray * 3 + 1], oz = rays_o[ray * 3 + 2];
    float dx = rays_d[ray * 3 + 0], dy = rays_d[ray * 3 + 1], dz = rays_d[ray * 3 + 2];
    float a0x = aabb[0], a0y = aabb[1], a0z = aabb[2];
    float a1x = aabb[3], a1y = aabb[4], a1z = aabb[5];
    float ix = 1.f / dx, iy = 1.f / dy, iz = 1.f / dz;
    float t1x = (a0x - ox) * ix, t2x = (a1x - ox) * ix;
    float t1y = (a0y - oy) * iy, t2y = (a1y - oy) * iy;
    float t1z = (a0z - oz) * iz, t2z = (a1z - oz) * iz;
    float tn = fmaxf(fmaxf(fminf(t1x, t2x), fminf(t1y, t2y)), fminf(t1z, t2z));
    tn = fmaxf(tn, 0.f);
    float tf = fminf(fminf(fmaxf(t1x, t2x), fmaxf(t1y, t2y)), fmaxf(t1z, t2z));
    tf = fminf(tf, 10.f);
    bool active = tn < tf;
    if (!active) { tn = 0.f; tf = 1.f; }
    float dnorm = sqrtf(dx * dx + dy * dy + dz * dz);

    if (tid == 0) {
        float inv = 1.f / dnorm;
        float x = dx * inv, y = dy * inv, z = dz * inv;
        float x2 = x * x, y2 = y * y, z2 = z * z;
        synm[0]  = 0.282094791773878f;
        synm[1]  = -0.488602511902920f * y;
        synm[2]  = 0.488602511902920f * z;
        synm[3]  = -0.488602511902920f * x;
        synm[4]  = 1.092548430592079f * x * y;
        synm[5]  = -1.092548430592079f * y * z;
        synm[6]  = 0.315391565252520f * (3.0f * z2 - 1.0f);
        synm[7]  = -1.092548430592079f * x * z;
        synm[8]  = 0.546274215296040f * (x2 - y2);
        synm[9]  = -0.590043589926644f * y * (3.0f * x2 - y2);
        synm[10] = 2.890611442640554f * x * y * z;
        synm[11] = -0.457045799464466f * y * (5.0f * z2 - 1.0f);
        synm[12] = 0.373176332590115f * z * (5.0f * z2 - 3.0f);
        synm[13] = -0.457045799464466f * x * (5.0f * z2 - 1.0f);
        synm[14] = 1.445305721320277f * z * (x2 - y2);
        synm[15] = -0.590043589926644f * x * (x2 - 3.0f * y2);
    }

    if (tid < 64) {
        float fr = (tid + 0.5f) * (1.f / 64.f);
        float t = tn + fr * (tf - tn);
        sts[tid] = t;
        float px = fmaf(dx, t, ox), py = fmaf(dy, t, oy), pz = fmaf(dz, t, oz);
        float nx = (px - a0x) / (a1x - a0x) * 2.f - 1.f;
        float ny = (py - a0y) / (a1y - a0y) * 2.f - 1.f;
        float nz = (pz - a0z) / (a1z - a0z) * 2.f - 1.f;
        sxyz[tid * 3 + 0] = nx;
        sxyz[tid * 3 + 1] = ny;
        sxyz[tid * 3 + 2] = nz;
        bool inside = (nx >= -1.f) && (nx <= 1.f) && (ny >= -1.f) && (ny <= 1.f) &&
                      (nz >= -1.f) && (nz <= 1.f);
        sins[tid] = inside ? 1.f : 0.f;
    }
    __syncthreads();  // (1)

    // ---- layer 1: h1T[j][p] = relu(xyz_ndc . W1[:,j] + b1[j]) ----
    {
        int p = tid & 63;
        int j0 = (tid >> 6) * 64;
        float nx = sxyz[p * 3], ny = sxyz[p * 3 + 1], nz = sxyz[p * 3 + 2];
#pragma unroll 4
        for (int j = j0; j < j0 + 64; j++) {
            float v = __ldg(b1 + j);
            v = fmaf(nx, __ldg(W1 + j), v);
            v = fmaf(ny, __ldg(W1 + 128 + j), v);
            v = fmaf(nz, __ldg(W1 + 256 + j), v);
            bufA[j * STR + p] = fmaxf(v, 0.f);
        }
        // fill ynm rows of in32 (rows 16..31)
        for (int idx = tid; idx < 16 * 64; idx += 128) {
            int i = idx >> 6, pp = idx & 63;
            in32[(16 + i) * STR + pp] = synm[i];
        }
    }
    __syncthreads();  // (2)

    // ---- layer 2: h2 = relu(h1 @ W2 + b2)  (big GEMM, FFMA2, W2 via L1) ----
    ull acc[4][8];
#pragma unroll
    for (int c = 0; c < 4; c++)
#pragma unroll
        for (int i = 0; i < 8; i++) acc[c][i] = 0ULL;
    gemm_tileG<HID>(W2, bufA, tx, pb, acc);
    __syncthreads();  // (3) all h1T reads done
    write_tileG(bufA, b2, tx, pb, acc);  // h2T overwrites h1T
    __syncthreads();  // (4)

    // ---- sigma + feat as padded 32-col mini-GEMM (cols: 0..15 feat, 16 sigma) ----
    {
        ull acc1[8];
#pragma unroll
        for (int i = 0; i < 8; i++) acc1[i] = 0ULL;
#pragma unroll 4
        for (int k = 0; k < HID; k++) {
            float w = 0.f;
            if (tx < 16) w = __ldg(Wf + k * 16 + tx);
            else if (tx == 16) w = __ldg(Wd + k);
            ull wp = pack2(w, w);
            const ulonglong2* hp = (const ulonglong2*)(bufA + k * STR + pb);
            ulonglong2 u0 = hp[0], u1 = hp[1], u2 = hp[2], u3 = hp[3];
            fma2(acc1[0], wp, u0.x);
            fma2(acc1[1], wp, u0.y);
            fma2(acc1[2], wp, u1.x);
            fma2(acc1[3], wp, u1.y);
            fma2(acc1[4], wp, u2.x);
            fma2(acc1[5], wp, u2.y);
            fma2(acc1[6], wp, u3.x);
            fma2(acc1[7], wp, u3.y);
        }
        float bb = 0.f;
        if (tx < 16) bb = __ldg(bf + tx);
        else if (tx == 16) bb = __ldg(bd);
        float v[16];
#pragma unroll
        for (int i = 0; i < 8; i++) {
            float lo, hi;
            unpack2(acc1[i], lo, hi);
            v[2 * i]     = lo + bb;
            v[2 * i + 1] = hi + bb;
        }
        if (tx < 16) {
            float4* d = (float4*)(in32 + tx * STR + pb);
            d[0] = make_float4(v[0], v[1], v[2], v[3]);
            d[1] = make_float4(v[4], v[5], v[6], v[7]);
            d[2] = make_float4(v[8], v[9], v[10], v[11]);
            d[3] = make_float4(v[12], v[13], v[14], v[15]);
        } else if (tx == 16) {
#pragma unroll
            for (int i = 0; i < 16; i++)
                ssig[pb + i] = expf(v[i]) * sins[pb + i];  // sigma masked by inside
        }
    }
    __syncthreads();  // (5)

    // ---- layer c1: hc = relu([feat, ynm] @ Wc1 + bc1), K=32 ----
    ull acc2[4][8];
#pragma unroll
    for (int c = 0; c < 4; c++)
#pragma unroll
        for (int i = 0; i < 8; i++) acc2[c][i] = 0ULL;
    gemm_tileG<32>(Wc1, in32, tx, pb, acc2);
    write_tileG(bufA, bc1, tx, pb, acc2);  // writes bufA; reads were from in32
    __syncthreads();  // (6)

    // ---- layer c2: color = sigmoid(hc @ Wc2 + bc2) ----
    float c0l = 0.f, c1l = 0.f;
    {
        int p = tid & 63;
        if (tid < 64) {
            float a0 = 0.f, a1 = 0.f;
#pragma unroll 4
            for (int k = 0; k < HID; k++) {
                float hv = bufA[k * STR + p];
                a0 = fmaf(hv, __ldg(Wc2 + k * 3 + 0), a0);
                a1 = fmaf(hv, __ldg(Wc2 + k * 3 + 1), a1);
            }
            c0l = 1.f / (1.f + expf(-(a0 + __ldg(bc2 + 0))));
            c1l = 1.f / (1.f + expf(-(a1 + __ldg(bc2 + 1))));
        } else {
            float a2 = 0.f;
#pragma unroll 4
            for (int k = 0; k < HID; k++) {
                float hv = bufA[k * STR + p];
                a2 = fmaf(hv, __ldg(Wc2 + k * 3 + 2), a2);
            }
            scol2[p] = 1.f / (1.f + expf(-(a2 + __ldg(bc2 + 2))));
        }
    }
    __syncthreads();  // (7)

    // ---- integration: warp-shuffle scan + reductions (threads 0..63) ----
    const int lane = tid & 31;
    const int wrp = tid >> 5;
    float tau = 0.f, tcur = 0.f, sc = 0.f;
    if (wrp < 2) {
        tcur = sts[tid];
        float tnext = (tid < 63) ? sts[tid + 1] : (tf + 1.0f);  // BOOSTER = 1.0
        tau = ssig[tid] * (tnext - tcur) * dnorm;
        sc = tau;
#pragma unroll
        for (int off = 1; off < 32; off <<= 1) {
            float u = __shfl_up_sync(0xffffffffu, sc, off);
            if (lane >= off) sc += u;
        }
        if (wrp == 0 && lane == 31) sred[15] = sc;
    }
    __syncthreads();  // (8)
    if (wrp < 2) {
        if (wrp == 1) sc += sred[15];
        float excl = sc - tau;
        float wgt = expf(-excl) * (1.f - expf(-tau));
        float v0 = wgt * c0l;
        float v1 = wgt * c1l;
        float v2 = wgt * scol2[tid];
        float v3 = wgt;
        float v4 = wgt * tcur;
#pragma unroll
        for (int off = 16; off >= 1; off >>= 1) {
            v0 += __shfl_xor_sync(0xffffffffu, v0, off);
            v1 += __shfl_xor_sync(0xffffffffu, v1, off);
            v2 += __shfl_xor_sync(0xffffffffu, v2, off);
            v3 += __shfl_xor_sync(0xffffffffu, v3, off);
            v4 += __shfl_xor_sync(0xffffffffu, v4, off);
        }
        if (lane == 0) {
            sred[wrp * 5 + 0] = v0;
            sred[wrp * 5 + 1] = v1;
            sred[wrp * 5 + 2] = v2;
            sred[wrp * 5 + 3] = v3;
            sred[wrp * 5 + 4] = v4;
        }
    }
    __syncthreads();  // (9)
    if (tid < 5) {
        float am = active ? 1.f : 0.f;
        out[ray * 5 + tid] = (sred[tid] + sred[5 + tid]) * am;
    }
}

extern "C" void kernel_launch(void* const* d_in, const int* in_sizes, int n_in,
                              void* d_out, int out_size) {
    const float* rays_o = (const float*)d_in[0];
    const float* rays_d = (const float*)d_in[1];
    const float* aabb   = (const float*)d_in[2];
    const float* W1  = (const float*)d_in[3];
    const float* b1  = (const float*)d_in[4];
    const float* W2  = (const float*)d_in[5];
    const float* b2  = (const float*)d_in[6];
    const float* Wd  = (const float*)d_in[7];
    const float* bd  = (const float*)d_in[8];
    const float* Wf  = (const float*)d_in[9];
    const float* bf  = (const float*)d_in[10];
    const float* Wc1 = (const float*)d_in[11];
    const float* bc1 = (const float*)d_in[12];
    const float* Wc2 = (const float*)d_in[13];
    const float* bc2 = (const float*)d_in[14];
    float* out = (float*)d_out;

    int n_rays = in_sizes[0] / 3;
    size_t smem = 11360 * sizeof(float);  // 45440 B -> 3 blocks/SM
    radiance_kernel<<<n_rays, 128, smem>>>(rays_o, rays_d, aabb, W1, b1, W2, b2, Wd, bd,
                                           Wf, bf, Wc1, bc1, Wc2, bc2, out);
}

// round 4
// speedup vs baseline: 1.1002x; 1.1002x over previous
#include <cuda_runtime.h>
#include <cstdint>

// ----------------------------------------------------------------------------
// RadianceRenderer R4 (= R3 + missing include fixed): W2/Wf/Wc1 streamed
// through 2x8KB smem chunks (cp.async, depth-1 pipeline) -> 65.9KB smem ->
// 3 blocks/SM (12 warps). Inner loops keep all-LDS operands.
// Block = 1 ray (64 points), 128 threads.
// ----------------------------------------------------------------------------

#define HID 128
#define STR 68        // padded row stride (floats); col writes are conflict-free
#define CK  16        // k-rows per streamed weight chunk (2048 floats = 8KB)

typedef unsigned long long ull;
typedef unsigned int u32;

__device__ __forceinline__ ull pack2(float lo, float hi) {
    ull r;
    asm("mov.b64 %0, {%1, %2};" : "=l"(r)
        : "r"(__float_as_uint(lo)), "r"(__float_as_uint(hi)));
    return r;
}
__device__ __forceinline__ void unpack2(ull v, float& lo, float& hi) {
    unsigned a, b;
    asm("mov.b64 {%0, %1}, %2;" : "=r"(a), "=r"(b) : "l"(v));
    lo = __uint_as_float(a);
    hi = __uint_as_float(b);
}
__device__ __forceinline__ void fma2(ull& d, ull a, ull b) {
    asm("fma.rn.f32x2 %0, %1, %2, %0;" : "+l"(d) : "l"(a), "l"(b));
}

__device__ __forceinline__ void cpa16(u32 dst, const void* src) {
    asm volatile("cp.async.ca.shared.global [%0], [%1], 16;" :: "r"(dst), "l"(src));
}
__device__ __forceinline__ void cpa_commit() {
    asm volatile("cp.async.commit_group;" ::: "memory");
}
template <int N>
__device__ __forceinline__ void cpa_wait() {
    asm volatile("cp.async.wait_group %0;" :: "n"(N) : "memory");
}

// prefetch one 2048-float (8KB) chunk: 512 x 16B, 4 per thread
__device__ __forceinline__ void pf_chunk(float* dstf, const float* src, int tid) {
    u32 d = (u32)__cvta_generic_to_shared(dstf);
#pragma unroll
    for (int i = 0; i < 4; i++)
        cpa16(d + (u32)(tid + i * 128) * 16u, src + (tid + i * 128) * 4);
}

// GEMM chunk: 64 points x 128 cols x CK k-rows, accumulate.
// Thread (tx,ty): cols [tx*4, tx*4+4), points [ty*16, ty*16+16).
// w: [CK][128] smem chunk.  a: transposed activations [CK][STR] slice in smem.
__device__ __forceinline__ void gemm_chunk(const float* __restrict__ w,
                                           const float* __restrict__ a,
                                           int cb, int pb, ull acc[4][8]) {
#pragma unroll 4
    for (int k = 0; k < CK; k++) {
        float4 w4 = *(const float4*)(w + k * HID + cb);
        ull wp0 = pack2(w4.x, w4.x);
        ull wp1 = pack2(w4.y, w4.y);
        ull wp2 = pack2(w4.z, w4.z);
        ull wp3 = pack2(w4.w, w4.w);
        const ulonglong2* hp = (const ulonglong2*)(a + k * STR + pb);
        ulonglong2 u0 = hp[0], u1 = hp[1], u2 = hp[2], u3 = hp[3];
        ull hh[8] = {u0.x, u0.y, u1.x, u1.y, u2.x, u2.y, u3.x, u3.y};
#pragma unroll
        for (int i = 0; i < 8; i++) {
            fma2(acc[0][i], wp0, hh[i]);
            fma2(acc[1][i], wp1, hh[i]);
            fma2(acc[2][i], wp2, hh[i]);
            fma2(acc[3][i], wp3, hh[i]);
        }
    }
}

// Write tile transposed (dst[col][p]) with bias + relu. Conflict-free STS.128.
__device__ __forceinline__ void write_tile(float* __restrict__ dst,
                                           const float* __restrict__ biasg,
                                           int cb, int pb, ull acc[4][8]) {
#pragma unroll
    for (int c = 0; c < 4; c++) {
        float bb = __ldg(biasg + cb + c);
        float v[16];
#pragma unroll
        for (int i = 0; i < 8; i++) {
            float lo, hi;
            unpack2(acc[c][i], lo, hi);
            v[2 * i]     = fmaxf(lo + bb, 0.f);
            v[2 * i + 1] = fmaxf(hi + bb, 0.f);
        }
        float4* d = (float4*)(dst + (cb + c) * STR + pb);
        d[0] = make_float4(v[0], v[1], v[2], v[3]);
        d[1] = make_float4(v[4], v[5], v[6], v[7]);
        d[2] = make_float4(v[8], v[9], v[10], v[11]);
        d[3] = make_float4(v[12], v[13], v[14], v[15]);
    }
}

__global__ __launch_bounds__(128, 3) void radiance_kernel(
    const float* __restrict__ rays_o, const float* __restrict__ rays_d,
    const float* __restrict__ aabb,
    const float* __restrict__ W1, const float* __restrict__ b1,
    const float* __restrict__ W2, const float* __restrict__ b2,
    const float* __restrict__ Wd, const float* __restrict__ bd,
    const float* __restrict__ Wf, const float* __restrict__ bf,
    const float* __restrict__ Wc1, const float* __restrict__ bc1,
    const float* __restrict__ Wc2, const float* __restrict__ bc2,
    float* __restrict__ out) {
    extern __shared__ float sm[];
    float* bufA  = sm;            // 8704  [128][STR]  h1T -> h2T -> hcT
    float* in32  = sm + 8704;     // 2176  [32][STR]: feat rows 0..15, ynm 16..31
    float* wbuf0 = sm + 10880;    // 2048  streamed weight chunk A
    float* wbuf1 = sm + 12928;    // 2048  streamed weight chunk B
    float* wsm   = sm + 14976;    // 1024: W1[0..384) b1[384..512) Wd[512..640) Wc2[640..1024)
    float* sxyz  = sm + 16000;    // 192
    float* sts   = sm + 16192;    // 64
    float* ssig  = sm + 16256;    // 64
    float* sins  = sm + 16320;    // 64
    float* synm  = sm + 16384;    // 16
    float* scol2 = sm + 16400;    // 64
    float* sred  = sm + 16464;    // 16
    float* wbuf[2] = {wbuf0, wbuf1};

    const int tid = threadIdx.x;
    const int ray = blockIdx.x;
    const int tx = tid & 31, ty = tid >> 5;
    const int cb = tx * 4, pb = ty * 16;

    // ---- group 0: small weights + W2 chunk 0 ----
    {
        u32 wu = (u32)__cvta_generic_to_shared(wsm);
        if (tid < 96) cpa16(wu + tid * 16u, W1 + tid * 4);
        else cpa16(wu + 1536u + (tid - 96) * 16u, b1 + (tid - 96) * 4);
        if (tid < 32) cpa16(wu + 2048u + tid * 16u, Wd + tid * 4);
        if (tid < 96) cpa16(wu + 2560u + tid * 16u, Wc2 + tid * 4);
        pf_chunk(wbuf0, W2, tid);
        cpa_commit();
    }

    // ---- ray setup (all threads, redundant & deterministic) ----
    float ox = rays_o[ray * 3 + 0], oy = rays_o[ray * 3 + 1], oz = rays_o[ray * 3 + 2];
    float dx = rays_d[ray * 3 + 0], dy = rays_d[ray * 3 + 1], dz = rays_d[ray * 3 + 2];
    float a0x = aabb[0], a0y = aabb[1], a0z = aabb[2];
    float a1x = aabb[3], a1y = aabb[4], a1z = aabb[5];
    float ix = 1.f / dx, iy = 1.f / dy, iz = 1.f / dz;
    float t1x = (a0x - ox) * ix, t2x = (a1x - ox) * ix;
    float t1y = (a0y - oy) * iy, t2y = (a1y - oy) * iy;
    float t1z = (a0z - oz) * iz, t2z = (a1z - oz) * iz;
    float tn = fmaxf(fmaxf(fminf(t1x, t2x), fminf(t1y, t2y)), fminf(t1z, t2z));
    tn = fmaxf(tn, 0.f);
    float tf = fminf(fminf(fmaxf(t1x, t2x), fmaxf(t1y, t2y)), fmaxf(t1z, t2z));
    tf = fminf(tf, 10.f);
    bool active = tn < tf;
    if (!active) { tn = 0.f; tf = 1.f; }
    float dnorm = sqrtf(dx * dx + dy * dy + dz * dz);

    if (tid == 0) {
        float inv = 1.f / dnorm;
        float x = dx * inv, y = dy * inv, z = dz * inv;
        float x2 = x * x, y2 = y * y, z2 = z * z;
        synm[0]  = 0.282094791773878f;
        synm[1]  = -0.488602511902920f * y;
        synm[2]  = 0.488602511902920f * z;
        synm[3]  = -0.488602511902920f * x;
        synm[4]  = 1.092548430592079f * x * y;
        synm[5]  = -1.092548430592079f * y * z;
        synm[6]  = 0.315391565252520f * (3.0f * z2 - 1.0f);
        synm[7]  = -1.092548430592079f * x * z;
        synm[8]  = 0.546274215296040f * (x2 - y2);
        synm[9]  = -0.590043589926644f * y * (3.0f * x2 - y2);
        synm[10] = 2.890611442640554f * x * y * z;
        synm[11] = -0.457045799464466f * y * (5.0f * z2 - 1.0f);
        synm[12] = 0.373176332590115f * z * (5.0f * z2 - 3.0f);
        synm[13] = -0.457045799464466f * x * (5.0f * z2 - 1.0f);
        synm[14] = 1.445305721320277f * z * (x2 - y2);
        synm[15] = -0.590043589926644f * x * (x2 - 3.0f * y2);
    }

    if (tid < 64) {
        float fr = (tid + 0.5f) * (1.f / 64.f);
        float t = tn + fr * (tf - tn);
        sts[tid] = t;
        float px = fmaf(dx, t, ox), py = fmaf(dy, t, oy), pz = fmaf(dz, t, oz);
        float nx = (px - a0x) / (a1x - a0x) * 2.f - 1.f;
        float ny = (py - a0y) / (a1y - a0y) * 2.f - 1.f;
        float nz = (pz - a0z) / (a1z - a0z) * 2.f - 1.f;
        sxyz[tid * 3 + 0] = nx;
        sxyz[tid * 3 + 1] = ny;
        sxyz[tid * 3 + 2] = nz;
        bool inside = (nx >= -1.f) && (nx <= 1.f) && (ny >= -1.f) && (ny <= 1.f) &&
                      (nz >= -1.f) && (nz <= 1.f);
        sins[tid] = inside ? 1.f : 0.f;
    }

    cpa_wait<0>();
    __syncthreads();  // (1) wsm + W2c0 ready, setup writes visible

    // prefetch W2 chunk 1 (overlaps layer-1 compute)
    pf_chunk(wbuf1, W2 + 1 * CK * HID, tid);
    cpa_commit();

    // ---- layer 1: h1T[j][p] = relu(xyz_ndc . W1[:,j] + b1[j]) ----
    {
        int p = tid & 63;
        int j0 = (tid >> 6) * 64;
        float nx = sxyz[p * 3], ny = sxyz[p * 3 + 1], nz = sxyz[p * 3 + 2];
#pragma unroll 4
        for (int j = j0; j < j0 + 64; j++) {
            float v = wsm[384 + j];
            v = fmaf(nx, wsm[j], v);
            v = fmaf(ny, wsm[128 + j], v);
            v = fmaf(nz, wsm[256 + j], v);
            bufA[j * STR + p] = fmaxf(v, 0.f);
        }
        // fill ynm rows of in32 (rows 16..31)
        for (int idx = tid; idx < 16 * 64; idx += 128) {
            int i = idx >> 6, pp = idx & 63;
            in32[(16 + i) * STR + pp] = synm[i];
        }
    }
    __syncthreads();  // (2) bufA(h1) ready

    // ---- layer 2: h2 = relu(h1 @ W2 + b2), streamed chunks ----
    ull acc[4][8];
#pragma unroll
    for (int c = 0; c < 4; c++)
#pragma unroll
        for (int i = 0; i < 8; i++) acc[c][i] = 0ULL;

#pragma unroll 1
    for (int c = 0; c < 8; c++) {
        cpa_wait<0>();
        __syncthreads();  // chunk c resident & visible; prior readers done
        // prefetch next virtual chunk: c+1<8 -> W2; c+1==8 -> Wf
        if (c + 1 < 8) pf_chunk(wbuf[(c + 1) & 1], W2 + (c + 1) * CK * HID, tid);
        else           pf_chunk(wbuf[0], Wf, tid);  // vchunk 8 -> wbuf0
        cpa_commit();
        gemm_chunk(wbuf[c & 1], bufA + c * CK * STR, cb, pb, acc);
    }
    write_tile(bufA, b2, cb, pb, acc);  // h2T (registers -> bufA)

    cpa_wait<0>();
    __syncthreads();  // (3) Wf in wbuf0; h2 visible
    pf_chunk(wbuf1, Wc1, tid);  // vchunk 9: Wc1 rows 0..15 -> wbuf1
    cpa_commit();

    // ---- sigma + feat as padded 32-col mini-GEMM (cols 0..15 feat, 16 sigma) ----
    {
        ull acc1[8];
#pragma unroll
        for (int i = 0; i < 8; i++) acc1[i] = 0ULL;
#pragma unroll 4
        for (int k = 0; k < HID; k++) {
            float w = 0.f;
            if (tx < 16) w = wbuf0[k * 16 + tx];
            else if (tx == 16) w = wsm[512 + k];
            ull wp = pack2(w, w);
            const ulonglong2* hp = (const ulonglong2*)(bufA + k * STR + pb);
            ulonglong2 u0 = hp[0], u1 = hp[1], u2 = hp[2], u3 = hp[3];
            fma2(acc1[0], wp, u0.x);
            fma2(acc1[1], wp, u0.y);
            fma2(acc1[2], wp, u1.x);
            fma2(acc1[3], wp, u1.y);
            fma2(acc1[4], wp, u2.x);
            fma2(acc1[5], wp, u2.y);
            fma2(acc1[6], wp, u3.x);
            fma2(acc1[7], wp, u3.y);
        }
        float bb = 0.f;
        if (tx < 16) bb = __ldg(bf + tx);
        else if (tx == 16) bb = __ldg(bd);
        float v[16];
#pragma unroll
        for (int i = 0; i < 8; i++) {
            float lo, hi;
            unpack2(acc1[i], lo, hi);
            v[2 * i]     = lo + bb;
            v[2 * i + 1] = hi + bb;
        }
        if (tx < 16) {
            float4* d = (float4*)(in32 + tx * STR + pb);
            d[0] = make_float4(v[0], v[1], v[2], v[3]);
            d[1] = make_float4(v[4], v[5], v[6], v[7]);
            d[2] = make_float4(v[8], v[9], v[10], v[11]);
            d[3] = make_float4(v[12], v[13], v[14], v[15]);
        } else if (tx == 16) {
#pragma unroll
            for (int i = 0; i < 16; i++)
                ssig[pb + i] = expf(v[i]) * sins[pb + i];
        }
    }

    cpa_wait<0>();
    __syncthreads();  // (4) Wc1 rows 0..15 in wbuf1; in32/ssig visible
    pf_chunk(wbuf0, Wc1 + CK * HID, tid);  // vchunk 10: Wc1 rows 16..31 -> wbuf0
    cpa_commit();

    // ---- layer c1: hc = relu([feat, ynm] @ Wc1 + bc1), K=32 in 2 chunks ----
    ull acc2[4][8];
#pragma unroll
    for (int c = 0; c < 4; c++)
#pragma unroll
        for (int i = 0; i < 8; i++) acc2[c][i] = 0ULL;
    gemm_chunk(wbuf1, in32, cb, pb, acc2);              // k = 0..15 (feat)
    cpa_wait<0>();
    __syncthreads();  // (5) Wc1 rows 16..31 in wbuf0
    gemm_chunk(wbuf0, in32 + CK * STR, cb, pb, acc2);   // k = 16..31 (ynm)
    write_tile(bufA, bc1, cb, pb, acc2);                // hcT -> bufA
    __syncthreads();  // (6)

    // ---- layer c2: color = sigmoid(hc @ Wc2 + bc2) ----
    float c0l = 0.f, c1l = 0.f;
    {
        int p = tid & 63;
        if (tid < 64) {
            float a0 = 0.f, a1 = 0.f;
#pragma unroll 4
            for (int k = 0; k < HID; k++) {
                float hv = bufA[k * STR + p];
                a0 = fmaf(hv, wsm[640 + k * 3 + 0], a0);
                a1 = fmaf(hv, wsm[640 + k * 3 + 1], a1);
            }
            c0l = 1.f / (1.f + expf(-(a0 + __ldg(bc2 + 0))));
            c1l = 1.f / (1.f + expf(-(a1 + __ldg(bc2 + 1))));
        } else {
            float a2 = 0.f;
#pragma unroll 4
            for (int k = 0; k < HID; k++) {
                float hv = bufA[k * STR + p];
                a2 = fmaf(hv, wsm[640 + k * 3 + 2], a2);
            }
            scol2[p] = 1.f / (1.f + expf(-(a2 + __ldg(bc2 + 2))));
        }
    }
    __syncthreads();  // (7)

    // ---- integration: warp-shuffle scan + reductions (threads 0..63) ----
    const int lane = tid & 31;
    const int wrp = tid >> 5;
    float tau = 0.f, tcur = 0.f, sc = 0.f;
    if (wrp < 2) {
        tcur = sts[tid];
        float tnext = (tid < 63) ? sts[tid + 1] : (tf + 1.0f);  // BOOSTER = 1.0
        tau = ssig[tid] * (tnext - tcur) * dnorm;
        sc = tau;
#pragma unroll
        for (int off = 1; off < 32; off <<= 1) {
            float u = __shfl_up_sync(0xffffffffu, sc, off);
            if (lane >= off) sc += u;
        }
        if (wrp == 0 && lane == 31) sred[15] = sc;
    }
    __syncthreads();  // (8)
    if (wrp < 2) {
        if (wrp == 1) sc += sred[15];
        float excl = sc - tau;
        float wgt = expf(-excl) * (1.f - expf(-tau));
        float v0 = wgt * c0l;
        float v1 = wgt * c1l;
        float v2 = wgt * scol2[tid];
        float v3 = wgt;
        float v4 = wgt * tcur;
#pragma unroll
        for (int off = 16; off >= 1; off >>= 1) {
            v0 += __shfl_xor_sync(0xffffffffu, v0, off);
            v1 += __shfl_xor_sync(0xffffffffu, v1, off);
            v2 += __shfl_xor_sync(0xffffffffu, v2, off);
            v3 += __shfl_xor_sync(0xffffffffu, v3, off);
            v4 += __shfl_xor_sync(0xffffffffu, v4, off);
        }
        if (lane == 0) {
            sred[wrp * 5 + 0] = v0;
            sred[wrp * 5 + 1] = v1;
            sred[wrp * 5 + 2] = v2;
            sred[wrp * 5 + 3] = v3;
            sred[wrp * 5 + 4] = v4;
        }
    }
    __syncthreads();  // (9)
    if (tid < 5) {
        float am = active ? 1.f : 0.f;
        out[ray * 5 + tid] = (sred[tid] + sred[5 + tid]) * am;
    }
}

extern "C" void kernel_launch(void* const* d_in, const int* in_sizes, int n_in,
                              void* d_out, int out_size) {
    const float* rays_o = (const float*)d_in[0];
    const float* rays_d = (const float*)d_in[1];
    const float* aabb   = (const float*)d_in[2];
    const float* W1  = (const float*)d_in[3];
    const float* b1  = (const float*)d_in[4];
    const float* W2  = (const float*)d_in[5];
    const float* b2  = (const float*)d_in[6];
    const float* Wd  = (const float*)d_in[7];
    const float* bd  = (const float*)d_in[8];
    const float* Wf  = (const float*)d_in[9];
    const float* bf  = (const float*)d_in[10];
    const float* Wc1 = (const float*)d_in[11];
    const float* bc1 = (const float*)d_in[12];
    const float* Wc2 = (const float*)d_in[13];
    const float* bc2 = (const float*)d_in[14];
    float* out = (float*)d_out;

    int n_rays = in_sizes[0] / 3;
    size_t smem = 16480 * sizeof(float);  // 65920 B -> 3 blocks/SM
    cudaFuncSetAttribute(radiance_kernel, cudaFuncAttributeMaxDynamicSharedMemorySize,
                         (int)smem);
    radiance_kernel<<<n_rays, 128, smem>>>(rays_o, rays_d, aabb, W1, b1, W2, b2, Wd, bd,
                                           Wf, bf, Wc1, bc1, Wc2, bc2, out);
}

// round 5
// speedup vs baseline: 1.3866x; 1.2603x over previous
#include <cuda_runtime.h>
#include <cstdint>

// ----------------------------------------------------------------------------
// RadianceRenderer R5: 4 blocks/SM (52.6KB smem, <=128 regs), CK=8 streamed
// weight chunks, ynm folded into c1 accumulator init, all-lane sigma/feat/c2.
// Block = 1 ray (64 points), 128 threads.
// ----------------------------------------------------------------------------

#define HID 128
#define STR 68        // padded row stride (floats), 16B-aligned rows
#define CK  8         // k-rows per streamed weight chunk (1024 floats = 4KB)

typedef unsigned long long ull;
typedef unsigned int u32;

__device__ __forceinline__ ull pack2(float lo, float hi) {
    ull r;
    asm("mov.b64 %0, {%1, %2};" : "=l"(r)
        : "r"(__float_as_uint(lo)), "r"(__float_as_uint(hi)));
    return r;
}
__device__ __forceinline__ void unpack2(ull v, float& lo, float& hi) {
    unsigned a, b;
    asm("mov.b64 {%0, %1}, %2;" : "=r"(a), "=r"(b) : "l"(v));
    lo = __uint_as_float(a);
    hi = __uint_as_float(b);
}
__device__ __forceinline__ void fma2(ull& d, ull a, ull b) {
    asm("fma.rn.f32x2 %0, %1, %2, %0;" : "+l"(d) : "l"(a), "l"(b));
}

__device__ __forceinline__ void cpa16(u32 dst, const void* src) {
    asm volatile("cp.async.ca.shared.global [%0], [%1], 16;" :: "r"(dst), "l"(src));
}
__device__ __forceinline__ void cpa_commit() {
    asm volatile("cp.async.commit_group;" ::: "memory");
}
template <int N>
__device__ __forceinline__ void cpa_wait() {
    asm volatile("cp.async.wait_group %0;" :: "n"(N) : "memory");
}

// prefetch one 1024-float (4KB) chunk: 256 x 16B, 2 per thread
__device__ __forceinline__ void pf_chunk8(float* dstf, const float* src, int tid) {
    u32 d = (u32)__cvta_generic_to_shared(dstf);
    cpa16(d + (u32)tid * 16u, src + tid * 4);
    cpa16(d + (u32)(tid + 128) * 16u, src + (tid + 128) * 4);
}

// GEMM chunk: 64 points x 128 cols x K k-rows, accumulate.
// Thread (tx,ty): cols [tx*4, tx*4+4), points [ty*16, ty*16+16).
template <int K>
__device__ __forceinline__ void gemm_chunk(const float* __restrict__ w,
                                           const float* __restrict__ a,
                                           int cb, int pb, ull acc[4][8]) {
#pragma unroll 4
    for (int k = 0; k < K; k++) {
        float4 w4 = *(const float4*)(w + k * HID + cb);
        ull wp0 = pack2(w4.x, w4.x);
        ull wp1 = pack2(w4.y, w4.y);
        ull wp2 = pack2(w4.z, w4.z);
        ull wp3 = pack2(w4.w, w4.w);
        const ulonglong2* hp = (const ulonglong2*)(a + k * STR + pb);
        ulonglong2 u0 = hp[0], u1 = hp[1], u2 = hp[2], u3 = hp[3];
        ull hh[8] = {u0.x, u0.y, u1.x, u1.y, u2.x, u2.y, u3.x, u3.y};
#pragma unroll
        for (int i = 0; i < 8; i++) {
            fma2(acc[0][i], wp0, hh[i]);
            fma2(acc[1][i], wp1, hh[i]);
            fma2(acc[2][i], wp2, hh[i]);
            fma2(acc[3][i], wp3, hh[i]);
        }
    }
}

// Write tile transposed (dst[col][p]) with bias + relu.
__device__ __forceinline__ void write_tile(float* __restrict__ dst,
                                           const float* __restrict__ biasg,
                                           int cb, int pb, ull acc[4][8]) {
#pragma unroll
    for (int c = 0; c < 4; c++) {
        float bb = __ldg(biasg + cb + c);
        float v[16];
#pragma unroll
        for (int i = 0; i < 8; i++) {
            float lo, hi;
            unpack2(acc[c][i], lo, hi);
            v[2 * i]     = fmaxf(lo + bb, 0.f);
            v[2 * i + 1] = fmaxf(hi + bb, 0.f);
        }
        float4* d = (float4*)(dst + (cb + c) * STR + pb);
        d[0] = make_float4(v[0], v[1], v[2], v[3]);
        d[1] = make_float4(v[4], v[5], v[6], v[7]);
        d[2] = make_float4(v[8], v[9], v[10], v[11]);
        d[3] = make_float4(v[12], v[13], v[14], v[15]);
    }
}

__global__ __launch_bounds__(128, 4) void radiance_kernel(
    const float* __restrict__ rays_o, const float* __restrict__ rays_d,
    const float* __restrict__ aabb,
    const float* __restrict__ W1, const float* __restrict__ b1,
    const float* __restrict__ W2, const float* __restrict__ b2,
    const float* __restrict__ Wd, const float* __restrict__ bd,
    const float* __restrict__ Wf, const float* __restrict__ bf,
    const float* __restrict__ Wc1, const float* __restrict__ bc1,
    const float* __restrict__ Wc2, const float* __restrict__ bc2,
    float* __restrict__ out) {
    extern __shared__ float sm[];
    float* bufA  = sm;            // 8704  [128][STR]  h1T -> h2T -> hcT
    float* in16  = sm + 8704;     // 1088  [16][STR]: feat
    float* wbuf0 = sm + 9792;     // 1024  streamed weight chunk A
    float* wbuf1 = sm + 10816;    // 1024  streamed weight chunk B
    float* wsm   = sm + 11840;    // 1024: W1[0..384) b1[384..512) Wd[512..640) Wc2[640..1024)
    float* sxyz  = sm + 12864;    // 192
    float* sts   = sm + 13056;    // 64
    float* ssig  = sm + 13120;    // 64
    float* sins  = sm + 13184;    // 64
    float* synm  = sm + 13248;    // 16
    float* sc0   = sm + 13264;    // 64
    float* sc1   = sm + 13328;    // 64
    float* sc2   = sm + 13392;    // 64
    float* sred  = sm + 13456;    // 16

    const int tid = threadIdx.x;
    const int ray = blockIdx.x;
    const int tx = tid & 31, ty = tid >> 5;
    const int cb = tx * 4, pb = ty * 16;

    // ---- group 0: small weights + W2 chunk 0 ----
    {
        u32 wu = (u32)__cvta_generic_to_shared(wsm);
        if (tid < 96) cpa16(wu + tid * 16u, W1 + tid * 4);
        else cpa16(wu + 1536u + (tid - 96) * 16u, b1 + (tid - 96) * 4);
        if (tid < 32) cpa16(wu + 2048u + tid * 16u, Wd + tid * 4);
        if (tid < 96) cpa16(wu + 2560u + tid * 16u, Wc2 + tid * 4);
        pf_chunk8(wbuf0, W2, tid);
        cpa_commit();
    }

    // ---- ray setup (all threads, redundant & deterministic) ----
    float ox = rays_o[ray * 3 + 0], oy = rays_o[ray * 3 + 1], oz = rays_o[ray * 3 + 2];
    float dx = rays_d[ray * 3 + 0], dy = rays_d[ray * 3 + 1], dz = rays_d[ray * 3 + 2];
    float a0x = aabb[0], a0y = aabb[1], a0z = aabb[2];
    float a1x = aabb[3], a1y = aabb[4], a1z = aabb[5];
    float ix = 1.f / dx, iy = 1.f / dy, iz = 1.f / dz;
    float t1x = (a0x - ox) * ix, t2x = (a1x - ox) * ix;
    float t1y = (a0y - oy) * iy, t2y = (a1y - oy) * iy;
    float t1z = (a0z - oz) * iz, t2z = (a1z - oz) * iz;
    float tn = fmaxf(fmaxf(fminf(t1x, t2x), fminf(t1y, t2y)), fminf(t1z, t2z));
    tn = fmaxf(tn, 0.f);
    float tf = fminf(fminf(fmaxf(t1x, t2x), fmaxf(t1y, t2y)), fmaxf(t1z, t2z));
    tf = fminf(tf, 10.f);
    bool active = tn < tf;
    if (!active) { tn = 0.f; tf = 1.f; }
    float dnorm = sqrtf(dx * dx + dy * dy + dz * dz);

    if (tid == 0) {
        float inv = 1.f / dnorm;
        float x = dx * inv, y = dy * inv, z = dz * inv;
        float x2 = x * x, y2 = y * y, z2 = z * z;
        synm[0]  = 0.282094791773878f;
        synm[1]  = -0.488602511902920f * y;
        synm[2]  = 0.488602511902920f * z;
        synm[3]  = -0.488602511902920f * x;
        synm[4]  = 1.092548430592079f * x * y;
        synm[5]  = -1.092548430592079f * y * z;
        synm[6]  = 0.315391565252520f * (3.0f * z2 - 1.0f);
        synm[7]  = -1.092548430592079f * x * z;
        synm[8]  = 0.546274215296040f * (x2 - y2);
        synm[9]  = -0.590043589926644f * y * (3.0f * x2 - y2);
        synm[10] = 2.890611442640554f * x * y * z;
        synm[11] = -0.457045799464466f * y * (5.0f * z2 - 1.0f);
        synm[12] = 0.373176332590115f * z * (5.0f * z2 - 3.0f);
        synm[13] = -0.457045799464466f * x * (5.0f * z2 - 1.0f);
        synm[14] = 1.445305721320277f * z * (x2 - y2);
        synm[15] = -0.590043589926644f * x * (x2 - 3.0f * y2);
    }

    if (tid < 64) {
        float fr = (tid + 0.5f) * (1.f / 64.f);
        float t = tn + fr * (tf - tn);
        sts[tid] = t;
        float px = fmaf(dx, t, ox), py = fmaf(dy, t, oy), pz = fmaf(dz, t, oz);
        float nx = (px - a0x) / (a1x - a0x) * 2.f - 1.f;
        float ny = (py - a0y) / (a1y - a0y) * 2.f - 1.f;
        float nz = (pz - a0z) / (a1z - a0z) * 2.f - 1.f;
        sxyz[tid * 3 + 0] = nx;
        sxyz[tid * 3 + 1] = ny;
        sxyz[tid * 3 + 2] = nz;
        bool inside = (nx >= -1.f) && (nx <= 1.f) && (ny >= -1.f) && (ny <= 1.f) &&
                      (nz >= -1.f) && (nz <= 1.f);
        sins[tid] = inside ? 1.f : 0.f;
    }

    cpa_wait<0>();
    __syncthreads();  // (1) wsm + W2 chunk0 resident; setup writes visible

    pf_chunk8(wbuf1, W2 + 1 * CK * HID, tid);  // chunk 1, overlaps layer-1
    cpa_commit();

    // ---- layer 1: h1T[j][p] = relu(xyz_ndc . W1[:,j] + b1[j]) ----
    {
        int p = tid & 63;
        int j0 = (tid >> 6) * 64;
        float nx = sxyz[p * 3], ny = sxyz[p * 3 + 1], nz = sxyz[p * 3 + 2];
#pragma unroll 4
        for (int j = j0; j < j0 + 64; j++) {
            float v = wsm[384 + j];
            v = fmaf(nx, wsm[j], v);
            v = fmaf(ny, wsm[128 + j], v);
            v = fmaf(nz, wsm[256 + j], v);
            bufA[j * STR + p] = fmaxf(v, 0.f);
        }
    }
    __syncthreads();  // (2) bufA(h1) ready

    // ---- layer 2: h2 = relu(h1 @ W2 + b2), 16 streamed CK=8 chunks ----
    // vchunks: 0..15 = W2, 16 = Wf rows 0..63, 17 = Wf rows 64..127
    ull acc[4][8];
#pragma unroll
    for (int c = 0; c < 4; c++)
#pragma unroll
        for (int i = 0; i < 8; i++) acc[c][i] = 0ULL;

#pragma unroll 1
    for (int c = 0; c < 16; c++) {
        gemm_chunk<CK>((c & 1) ? wbuf1 : wbuf0, bufA + c * CK * STR, cb, pb, acc);
        cpa_wait<0>();    // next chunk (c+1) resident
        __syncthreads();  // all warps done with chunk c's buffer
        int nx2 = c + 2;
        if (nx2 <= 17) {
            const float* src = (nx2 < 16) ? (W2 + nx2 * CK * HID)
                                          : ((nx2 == 16) ? Wf : Wf + 1024);
            pf_chunk8((c & 1) ? wbuf1 : wbuf0, src, tid);
            cpa_commit();
        }
    }
    // all warps synced after last gemm; safe to overwrite bufA with h2
    write_tile(bufA, b2, cb, pb, acc);
    __syncthreads();  // (3) h2 visible; wbuf0 = Wf rows 0..63 (drained at c=15)

    // ---- feat: 64 pts x 16 cols, K=128, all lanes busy ----
    // thread: col = tx&15, points [ty*16 + (tx>>4)*8, +8)
    const int fcol = tx & 15;
    const int pb2 = pb + (tx >> 4) * 8;
    ull fa[4];
#pragma unroll
    for (int i = 0; i < 4; i++) fa[i] = 0ULL;
#pragma unroll 4
    for (int k = 0; k < 64; k++) {
        float w = wbuf0[k * 16 + fcol];
        ull wp = pack2(w, w);
        const ulonglong2* hp = (const ulonglong2*)(bufA + k * STR + pb2);
        ulonglong2 u0 = hp[0], u1 = hp[1];
        fma2(fa[0], wp, u0.x);
        fma2(fa[1], wp, u0.y);
        fma2(fa[2], wp, u1.x);
        fma2(fa[3], wp, u1.y);
    }
    cpa_wait<0>();    // Wf rows 64..127 resident in wbuf1
    __syncthreads();  // (4) all warps done reading wbuf0
    pf_chunk8(wbuf0, Wc1, tid);  // Wc1 rows 0..7
    cpa_commit();
#pragma unroll 4
    for (int k = 0; k < 64; k++) {
        float w = wbuf1[k * 16 + fcol];
        ull wp = pack2(w, w);
        const ulonglong2* hp = (const ulonglong2*)(bufA + (64 + k) * STR + pb2);
        ulonglong2 u0 = hp[0], u1 = hp[1];
        fma2(fa[0], wp, u0.x);
        fma2(fa[1], wp, u0.y);
        fma2(fa[2], wp, u1.x);
        fma2(fa[3], wp, u1.y);
    }
    {
        float bb = __ldg(bf + fcol);
        float v[8];
#pragma unroll
        for (int i = 0; i < 4; i++) {
            float lo, hi;
            unpack2(fa[i], lo, hi);
            v[2 * i]     = lo + bb;
            v[2 * i + 1] = hi + bb;
        }
        float4* d = (float4*)(in16 + fcol * STR + pb2);
        d[0] = make_float4(v[0], v[1], v[2], v[3]);
        d[1] = make_float4(v[4], v[5], v[6], v[7]);
    }

    // ---- sigma: split-k over 128 threads (2 threads per point) ----
    {
        int p = tid >> 1, half = tid & 1;
        int kb = half * 64;
        float s = 0.f;
#pragma unroll 4
        for (int k = 0; k < 64; k++)
            s = fmaf(bufA[(kb + k) * STR + p], wsm[512 + kb + k], s);
        float o = __shfl_xor_sync(0xffffffffu, s, 1);
        if (!half) ssig[p] = expf(s + o + __ldg(bd)) * sins[p];
    }
    cpa_wait<0>();    // Wc1 rows 0..7 resident
    __syncthreads();  // (5) in16/ssig visible; bufA(h2) readers done
    pf_chunk8(wbuf1, Wc1 + 1024, tid);  // Wc1 rows 8..15
    cpa_commit();

    // ---- layer c1: hc = relu([feat, ynm] @ Wc1 + bc1) ----
    // ynm part (k=16..31) is point-invariant: fold into accumulator init.
    {
        float y0 = 0.f, y1 = 0.f, y2 = 0.f, y3 = 0.f;
#pragma unroll
        for (int j = 0; j < 16; j++) {
            float s = synm[j];
            const float* wr = Wc1 + (16 + j) * HID + cb;
            y0 = fmaf(s, __ldg(wr + 0), y0);
            y1 = fmaf(s, __ldg(wr + 1), y1);
            y2 = fmaf(s, __ldg(wr + 2), y2);
            y3 = fmaf(s, __ldg(wr + 3), y3);
        }
#pragma unroll
        for (int i = 0; i < 8; i++) {
            acc[0][i] = pack2(y0, y0);
            acc[1][i] = pack2(y1, y1);
            acc[2][i] = pack2(y2, y2);
            acc[3][i] = pack2(y3, y3);
        }
    }
    gemm_chunk<CK>(wbuf0, in16, cb, pb, acc);              // k = 0..7
    cpa_wait<0>();
    __syncthreads();  // (6) Wc1 rows 8..15 resident
    gemm_chunk<CK>(wbuf1, in16 + CK * STR, cb, pb, acc);   // k = 8..15
    __syncthreads();  // (6b) all warps done reading bufA? (none read bufA here) — keeps hc write ordered vs sigma readers
    write_tile(bufA, bc1, cb, pb, acc);                    // hcT -> bufA
    __syncthreads();  // (7) hc visible

    // ---- layer c2: color = sigmoid(hc @ Wc2 + bc2), split-k all threads ----
    {
        int p = tid >> 1, half = tid & 1;
        int kb = half * 64;
        float a0 = 0.f, a1 = 0.f, a2 = 0.f;
#pragma unroll 4
        for (int k = 0; k < 64; k++) {
            float hv = bufA[(kb + k) * STR + p];
            const float* wr = wsm + 640 + (kb + k) * 3;
            a0 = fmaf(hv, wr[0], a0);
            a1 = fmaf(hv, wr[1], a1);
            a2 = fmaf(hv, wr[2], a2);
        }
        a0 += __shfl_xor_sync(0xffffffffu, a0, 1);
        a1 += __shfl_xor_sync(0xffffffffu, a1, 1);
        a2 += __shfl_xor_sync(0xffffffffu, a2, 1);
        if (!half) {
            sc0[p] = 1.f / (1.f + expf(-(a0 + __ldg(bc2 + 0))));
            sc1[p] = 1.f / (1.f + expf(-(a1 + __ldg(bc2 + 1))));
            sc2[p] = 1.f / (1.f + expf(-(a2 + __ldg(bc2 + 2))));
        }
    }
    __syncthreads();  // (8)

    // ---- integration: warp-shuffle scan + reductions (threads 0..63) ----
    const int lane = tid & 31;
    const int wrp = tid >> 5;
    float tau = 0.f, tcur = 0.f, sc = 0.f;
    if (wrp < 2) {
        tcur = sts[tid];
        float tnext = (tid < 63) ? sts[tid + 1] : (tf + 1.0f);  // BOOSTER = 1.0
        tau = ssig[tid] * (tnext - tcur) * dnorm;
        sc = tau;
#pragma unroll
        for (int off = 1; off < 32; off <<= 1) {
            float u = __shfl_up_sync(0xffffffffu, sc, off);
            if (lane >= off) sc += u;
        }
        if (wrp == 0 && lane == 31) sred[15] = sc;
    }
    __syncthreads();  // (9)
    if (wrp < 2) {
        if (wrp == 1) sc += sred[15];
        float excl = sc - tau;
        float wgt = expf(-excl) * (1.f - expf(-tau));
        float v0 = wgt * sc0[tid];
        float v1 = wgt * sc1[tid];
        float v2 = wgt * sc2[tid];
        float v3 = wgt;
        float v4 = wgt * tcur;
#pragma unroll
        for (int off = 16; off >= 1; off >>= 1) {
            v0 += __shfl_xor_sync(0xffffffffu, v0, off);
            v1 += __shfl_xor_sync(0xffffffffu, v1, off);
            v2 += __shfl_xor_sync(0xffffffffu, v2, off);
            v3 += __shfl_xor_sync(0xffffffffu, v3, off);
            v4 += __shfl_xor_sync(0xffffffffu, v4, off);
        }
        if (lane == 0) {
            sred[wrp * 5 + 0] = v0;
            sred[wrp * 5 + 1] = v1;
            sred[wrp * 5 + 2] = v2;
            sred[wrp * 5 + 3] = v3;
            sred[wrp * 5 + 4] = v4;
        }
    }
    __syncthreads();  // (10)
    if (tid < 5) {
        float am = active ? 1.f : 0.f;
        out[ray * 5 + tid] = (sred[tid] + sred[5 + tid]) * am;
    }
}

extern "C" void kernel_launch(void* const* d_in, const int* in_sizes, int n_in,
                              void* d_out, int out_size) {
    const float* rays_o = (const float*)d_in[0];
    const float* rays_d = (const float*)d_in[1];
    const float* aabb   = (const float*)d_in[2];
    const float* W1  = (const float*)d_in[3];
    const float* b1  = (const float*)d_in[4];
    const float* W2  = (const float*)d_in[5];
    const float* b2  = (const float*)d_in[6];
    const float* Wd  = (const float*)d_in[7];
    const float* bd  = (const float*)d_in[8];
    const float* Wf  = (const float*)d_in[9];
    const float* bf  = (const float*)d_in[10];
    const float* Wc1 = (const float*)d_in[11];
    const float* bc1 = (const float*)d_in[12];
    const float* Wc2 = (const float*)d_in[13];
    const float* bc2 = (const float*)d_in[14];
    float* out = (float*)d_out;

    int n_rays = in_sizes[0] / 3;
    size_t smem = 13472 * sizeof(float);  // 53888 B -> 4 blocks/SM
    cudaFuncSetAttribute(radiance_kernel, cudaFuncAttributeMaxDynamicSharedMemorySize,
                         (int)smem);
    radiance_kernel<<<n_rays, 128, smem>>>(rays_o, rays_d, aabb, W1, b1, W2, b2, Wd, bd,
                                           Wf, bf, Wc1, bc1, Wc2, bc2, out);
}

// round 7
// speedup vs baseline: 2.0990x; 1.5137x over previous
#include <cuda_runtime.h>
#include <cuda_bf16.h>
#include <cstdint>

// ----------------------------------------------------------------------------
// RadianceRenderer R7: W2 layer via mma.sync.m16n8k16 bf16-split (HMMA, legal on
// sm_103 family target). A-fragments computed inline from W1; B-fragments
// pre-packed by prep kernel into fragment-ordered global (1 LDG.128 each).
// Rest = R5's verified scalar phases. Block = 1 ray, 128 threads, 3 blocks/SM.
// ----------------------------------------------------------------------------

#define HID 128
#define STR 68

typedef unsigned long long ull;
typedef unsigned int u32;

// fragment-ordered B: [ks(8)][nt(16)][lane(32)] -> uint4 {bhi0,bhi1,blo0,blo1}
__device__ __align__(16) uint4 g_Bf[8 * 16 * 32];

__device__ __forceinline__ ull pack2(float lo, float hi) {
    ull r;
    asm("mov.b64 %0, {%1, %2};" : "=l"(r)
        : "r"(__float_as_uint(lo)), "r"(__float_as_uint(hi)));
    return r;
}
__device__ __forceinline__ void unpack2(ull v, float& lo, float& hi) {
    unsigned a, b;
    asm("mov.b64 {%0, %1}, %2;" : "=r"(a), "=r"(b) : "l"(v));
    lo = __uint_as_float(a);
    hi = __uint_as_float(b);
}
__device__ __forceinline__ void fma2(ull& d, ull a, ull b) {
    asm("fma.rn.f32x2 %0, %1, %2, %0;" : "+l"(d) : "l"(a), "l"(b));
}
__device__ __forceinline__ void cpa16(u32 dst, const void* src) {
    asm volatile("cp.async.ca.shared.global [%0], [%1], 16;" :: "r"(dst), "l"(src));
}
__device__ __forceinline__ void cpa_commit() {
    asm volatile("cp.async.commit_group;" ::: "memory");
}
template <int N>
__device__ __forceinline__ void cpa_wait() {
    asm volatile("cp.async.wait_group %0;" :: "n"(N) : "memory");
}
__device__ __forceinline__ u32 smem_u32(const void* p) {
    return (u32)__cvta_generic_to_shared(p);
}

__device__ __forceinline__ void mma16816(float c[4], u32 a0, u32 a1, u32 a2, u32 a3,
                                         u32 b0, u32 b1) {
    asm volatile(
        "mma.sync.aligned.m16n8k16.row.col.f32.bf16.bf16.f32 "
        "{%0,%1,%2,%3}, {%4,%5,%6,%7}, {%8,%9}, {%0,%1,%2,%3};"
        : "+f"(c[0]), "+f"(c[1]), "+f"(c[2]), "+f"(c[3])
        : "r"(a0), "r"(a1), "r"(a2), "r"(a3), "r"(b0), "r"(b1));
}

__device__ __forceinline__ u32 pack_bf16x2(float v0, float v1) {
    __nv_bfloat16 h0 = __float2bfloat16(v0), h1 = __float2bfloat16(v1);
    return (u32)__bfloat16_as_ushort(h0) | ((u32)__bfloat16_as_ushort(h1) << 16);
}

// ---------- prep: W2 -> fragment-ordered bf16 hi/lo ----------
__global__ void prep_w2(const float* __restrict__ W2) {
    int b = blockIdx.x;            // 0..127 = ks*16+nt
    int lane = threadIdx.x;        // 32
    int ks = b >> 4, nt = b & 15;
    int k0 = ks * 16 + (lane & 3) * 2;
    int n = nt * 8 + (lane >> 2);
    float x0 = W2[k0 * 128 + n];
    float x1 = W2[(k0 + 1) * 128 + n];
    float x2 = W2[(k0 + 8) * 128 + n];
    float x3 = W2[(k0 + 9) * 128 + n];
    __nv_bfloat16 h0 = __float2bfloat16(x0), h1 = __float2bfloat16(x1);
    __nv_bfloat16 h2 = __float2bfloat16(x2), h3 = __float2bfloat16(x3);
    uint4 v;
    v.x = (u32)__bfloat16_as_ushort(h0) | ((u32)__bfloat16_as_ushort(h1) << 16);
    v.y = (u32)__bfloat16_as_ushort(h2) | ((u32)__bfloat16_as_ushort(h3) << 16);
    v.z = pack_bf16x2(x0 - __bfloat162float(h0), x1 - __bfloat162float(h1));
    v.w = pack_bf16x2(x2 - __bfloat162float(h2), x3 - __bfloat162float(h3));
    g_Bf[b * 32 + lane] = v;
}

// ---------- scalar helpers (verified in R5) ----------
template <int K>
__device__ __forceinline__ void gemm_chunk(const float* __restrict__ w,
                                           const float* __restrict__ a,
                                           int cb, int pb, ull acc[4][8]) {
#pragma unroll 4
    for (int k = 0; k < K; k++) {
        float4 w4 = *(const float4*)(w + k * HID + cb);
        ull wp0 = pack2(w4.x, w4.x);
        ull wp1 = pack2(w4.y, w4.y);
        ull wp2 = pack2(w4.z, w4.z);
        ull wp3 = pack2(w4.w, w4.w);
        const ulonglong2* hp = (const ulonglong2*)(a + k * STR + pb);
        ulonglong2 u0 = hp[0], u1 = hp[1], u2 = hp[2], u3 = hp[3];
        ull hh[8] = {u0.x, u0.y, u1.x, u1.y, u2.x, u2.y, u3.x, u3.y};
#pragma unroll
        for (int i = 0; i < 8; i++) {
            fma2(acc[0][i], wp0, hh[i]);
            fma2(acc[1][i], wp1, hh[i]);
            fma2(acc[2][i], wp2, hh[i]);
            fma2(acc[3][i], wp3, hh[i]);
        }
    }
}
__device__ __forceinline__ void write_tile(float* __restrict__ dst,
                                           const float* __restrict__ biasg,
                                           int cb, int pb, ull acc[4][8]) {
#pragma unroll
    for (int c = 0; c < 4; c++) {
        float bb = __ldg(biasg + cb + c);
        float v[16];
#pragma unroll
        for (int i = 0; i < 8; i++) {
            float lo, hi;
            unpack2(acc[c][i], lo, hi);
            v[2 * i]     = fmaxf(lo + bb, 0.f);
            v[2 * i + 1] = fmaxf(hi + bb, 0.f);
        }
        float4* d = (float4*)(dst + (cb + c) * STR + pb);
        d[0] = make_float4(v[0], v[1], v[2], v[3]);
        d[1] = make_float4(v[4], v[5], v[6], v[7]);
        d[2] = make_float4(v[8], v[9], v[10], v[11]);
        d[3] = make_float4(v[12], v[13], v[14], v[15]);
    }
}

__global__ __launch_bounds__(128, 3) void radiance_kernel(
    const float* __restrict__ rays_o, const float* __restrict__ rays_d,
    const float* __restrict__ aabb,
    const float* __restrict__ W1, const float* __restrict__ b1,
    const float* __restrict__ W2, const float* __restrict__ b2,
    const float* __restrict__ Wd, const float* __restrict__ bd,
    const float* __restrict__ Wf, const float* __restrict__ bf,
    const float* __restrict__ Wc1, const float* __restrict__ bc1,
    const float* __restrict__ Wc2, const float* __restrict__ bc2,
    float* __restrict__ out) {
    extern __shared__ float sm[];
    float* bufA = sm;           // [128][STR] h2T -> hcT
    float* in16 = sm + 8704;    // [16][STR] feat
    float* wsm  = sm + 9792;    // W1[0..384) b1[384..512) Wd[512..640) Wc2[640..1024) b2[1024..1152)
    float* sxyz = sm + 10944;   // 192
    float* sts  = sm + 11136;   // 64
    float* ssig = sm + 11200;   // 64
    float* sins = sm + 11264;   // 64
    float* synm = sm + 11328;   // 16
    float* sc0  = sm + 11344;   // 64
    float* sc1  = sm + 11408;   // 64
    float* sc2  = sm + 11472;   // 64
    float* sred = sm + 11536;   // 16

    const int tid = threadIdx.x;
    const int ray = blockIdx.x;
    const int wid = tid >> 5;
    const int lane = tid & 31;
    const int cb = lane * 4, pb = wid * 16;

    // ---- cp group 0: small weights ----
    {
        u32 wu = smem_u32(wsm);
        if (tid < 96) cpa16(wu + tid * 16u, W1 + tid * 4);
        else cpa16(wu + 1536u + (tid - 96) * 16u, b1 + (tid - 96) * 4);
        if (tid < 32) cpa16(wu + 2048u + tid * 16u, Wd + tid * 4);
        if (tid < 96) cpa16(wu + 2560u + tid * 16u, Wc2 + tid * 4);
        if (tid < 32) cpa16(wu + 4096u + tid * 16u, b2 + tid * 4);
        cpa_commit();
    }

    // ---- ray setup ----
    float ox = rays_o[ray * 3 + 0], oy = rays_o[ray * 3 + 1], oz = rays_o[ray * 3 + 2];
    float dx = rays_d[ray * 3 + 0], dy = rays_d[ray * 3 + 1], dz = rays_d[ray * 3 + 2];
    float a0x = aabb[0], a0y = aabb[1], a0z = aabb[2];
    float a1x = aabb[3], a1y = aabb[4], a1z = aabb[5];
    float ix = 1.f / dx, iy = 1.f / dy, iz = 1.f / dz;
    float t1x = (a0x - ox) * ix, t2x = (a1x - ox) * ix;
    float t1y = (a0y - oy) * iy, t2y = (a1y - oy) * iy;
    float t1z = (a0z - oz) * iz, t2z = (a1z - oz) * iz;
    float tn = fmaxf(fmaxf(fminf(t1x, t2x), fminf(t1y, t2y)), fminf(t1z, t2z));
    tn = fmaxf(tn, 0.f);
    float tf = fminf(fminf(fmaxf(t1x, t2x), fmaxf(t1y, t2y)), fmaxf(t1z, t2z));
    tf = fminf(tf, 10.f);
    bool active = tn < tf;
    if (!active) { tn = 0.f; tf = 1.f; }
    float dnorm = sqrtf(dx * dx + dy * dy + dz * dz);

    if (tid == 0) {
        float inv = 1.f / dnorm;
        float x = dx * inv, y = dy * inv, z = dz * inv;
        float x2 = x * x, y2 = y * y, z2 = z * z;
        synm[0]  = 0.282094791773878f;
        synm[1]  = -0.488602511902920f * y;
        synm[2]  = 0.488602511902920f * z;
        synm[3]  = -0.488602511902920f * x;
        synm[4]  = 1.092548430592079f * x * y;
        synm[5]  = -1.092548430592079f * y * z;
        synm[6]  = 0.315391565252520f * (3.0f * z2 - 1.0f);
        synm[7]  = -1.092548430592079f * x * z;
        synm[8]  = 0.546274215296040f * (x2 - y2);
        synm[9]  = -0.590043589926644f * y * (3.0f * x2 - y2);
        synm[10] = 2.890611442640554f * x * y * z;
        synm[11] = -0.457045799464466f * y * (5.0f * z2 - 1.0f);
        synm[12] = 0.373176332590115f * z * (5.0f * z2 - 3.0f);
        synm[13] = -0.457045799464466f * x * (5.0f * z2 - 1.0f);
        synm[14] = 1.445305721320277f * z * (x2 - y2);
        synm[15] = -0.590043589926644f * x * (x2 - 3.0f * y2);
    }
    if (tid < 64) {
        float fr = (tid + 0.5f) * (1.f / 64.f);
        float t = tn + fr * (tf - tn);
        sts[tid] = t;
        float px = fmaf(dx, t, ox), py = fmaf(dy, t, oy), pz = fmaf(dz, t, oz);
        float nx = (px - a0x) / (a1x - a0x) * 2.f - 1.f;
        float ny = (py - a0y) / (a1y - a0y) * 2.f - 1.f;
        float nz = (pz - a0z) / (a1z - a0z) * 2.f - 1.f;
        sxyz[tid * 3 + 0] = nx;
        sxyz[tid * 3 + 1] = ny;
        sxyz[tid * 3 + 2] = nz;
        bool inside = (nx >= -1.f) && (nx <= 1.f) && (ny >= -1.f) && (ny <= 1.f) &&
                      (nz >= -1.f) && (nz <= 1.f);
        sins[tid] = inside ? 1.f : 0.f;
    }
    cpa_wait<0>();
    __syncthreads();  // (1) wsm + setup visible

    // ---- W2 layer: h2 = relu(h1 @ W2 + b2) via HMMA bf16-split ----
    // warp wid owns points [wid*16, wid*16+16). Fragment rows: p0 = lane>>2, p1 = p0+8.
    {
        const int r0 = lane >> 2;
        const int p0 = pb + r0, p1 = p0 + 8;
        float P0x = sxyz[p0 * 3], P0y = sxyz[p0 * 3 + 1], P0z = sxyz[p0 * 3 + 2];
        float P1x = sxyz[p1 * 3], P1y = sxyz[p1 * 3 + 1], P1z = sxyz[p1 * 3 + 2];

        float c[16][4];
#pragma unroll
        for (int nt = 0; nt < 16; nt++)
#pragma unroll
            for (int i = 0; i < 4; i++) c[nt][i] = 0.f;

#pragma unroll 1
        for (int ks = 0; ks < 8; ks++) {
            int j0 = ks * 16 + (lane & 3) * 2;
            // 8 h1 values: (P0,P1) x (j0, j0+1, j0+8, j0+9)
            float v[8];
#pragma unroll
            for (int q = 0; q < 4; q++) {
                int j = j0 + (q & 1) + (q >> 1) * 8;
                float w0 = wsm[j], w1 = wsm[128 + j], w2 = wsm[256 + j], bb = wsm[384 + j];
                float h0 = fmaf(P0x, w0, bb);
                h0 = fmaf(P0y, w1, h0);
                h0 = fmaf(P0z, w2, h0);
                float h1v = fmaf(P1x, w0, bb);
                h1v = fmaf(P1y, w1, h1v);
                h1v = fmaf(P1z, w2, h1v);
                v[q] = fmaxf(h0, 0.f);       // P0, j-index q
                v[4 + q] = fmaxf(h1v, 0.f);  // P1
            }
            // pack A fragments (hi and lo)
            __nv_bfloat16 hh[8];
            u32 ahi[4], alo[4];
#pragma unroll
            for (int q = 0; q < 8; q++) hh[q] = __float2bfloat16(v[q]);
            ahi[0] = (u32)__bfloat16_as_ushort(hh[0]) | ((u32)__bfloat16_as_ushort(hh[1]) << 16);
            ahi[1] = (u32)__bfloat16_as_ushort(hh[4]) | ((u32)__bfloat16_as_ushort(hh[5]) << 16);
            ahi[2] = (u32)__bfloat16_as_ushort(hh[2]) | ((u32)__bfloat16_as_ushort(hh[3]) << 16);
            ahi[3] = (u32)__bfloat16_as_ushort(hh[6]) | ((u32)__bfloat16_as_ushort(hh[7]) << 16);
            alo[0] = pack_bf16x2(v[0] - __bfloat162float(hh[0]), v[1] - __bfloat162float(hh[1]));
            alo[1] = pack_bf16x2(v[4] - __bfloat162float(hh[4]), v[5] - __bfloat162float(hh[5]));
            alo[2] = pack_bf16x2(v[2] - __bfloat162float(hh[2]), v[3] - __bfloat162float(hh[3]));
            alo[3] = pack_bf16x2(v[6] - __bfloat162float(hh[6]), v[7] - __bfloat162float(hh[7]));

            const uint4* gb = g_Bf + ks * 16 * 32 + lane;
#pragma unroll
            for (int nt = 0; nt < 16; nt++) {
                uint4 B = __ldg(gb + nt * 32);
                mma16816(c[nt], ahi[0], ahi[1], ahi[2], ahi[3], B.x, B.y);  // hi*hi
                mma16816(c[nt], ahi[0], ahi[1], ahi[2], ahi[3], B.z, B.w);  // hi*lo
                mma16816(c[nt], alo[0], alo[1], alo[2], alo[3], B.x, B.y);  // lo*hi
            }
        }
        // writeback h2T with bias+relu (conflict-free pattern)
#pragma unroll
        for (int nt = 0; nt < 16; nt++) {
            int col0 = nt * 8 + (lane & 3) * 2;
            float bb0 = wsm[1024 + col0], bb1 = wsm[1024 + col0 + 1];
            bufA[col0 * STR + p0]       = fmaxf(c[nt][0] + bb0, 0.f);
            bufA[(col0 + 1) * STR + p0] = fmaxf(c[nt][1] + bb1, 0.f);
            bufA[col0 * STR + p1]       = fmaxf(c[nt][2] + bb0, 0.f);
            bufA[(col0 + 1) * STR + p1] = fmaxf(c[nt][3] + bb1, 0.f);
        }
    }
    __syncthreads();  // (2) h2 ready

    // ---- feat: 64 pts x 16 cols, K=128, all lanes; Wf via LDG ----
    {
        const int fcol = lane & 15;
        const int pb2 = pb + (lane >> 4) * 8;
        ull fa[4] = {0ULL, 0ULL, 0ULL, 0ULL};
#pragma unroll 4
        for (int k = 0; k < HID; k++) {
            float w = __ldg(Wf + k * 16 + fcol);
            ull wp = pack2(w, w);
            const ulonglong2* hp = (const ulonglong2*)(bufA + k * STR + pb2);
            ulonglong2 u0 = hp[0], u1 = hp[1];
            fma2(fa[0], wp, u0.x);
            fma2(fa[1], wp, u0.y);
            fma2(fa[2], wp, u1.x);
            fma2(fa[3], wp, u1.y);
        }
        float bb = __ldg(bf + fcol);
        float vv[8];
#pragma unroll
        for (int i = 0; i < 4; i++) {
            float lo, hi;
            unpack2(fa[i], lo, hi);
            vv[2 * i]     = lo + bb;
            vv[2 * i + 1] = hi + bb;
        }
        float4* d = (float4*)(in16 + fcol * STR + pb2);
        d[0] = make_float4(vv[0], vv[1], vv[2], vv[3]);
        d[1] = make_float4(vv[4], vv[5], vv[6], vv[7]);
    }
    // ---- sigma: split-k (2 threads per point) ----
    {
        int p = tid >> 1, half = tid & 1;
        int kb = half * 64;
        float s = 0.f;
#pragma unroll 4
        for (int k = 0; k < 64; k++)
            s = fmaf(bufA[(kb + k) * STR + p], wsm[512 + kb + k], s);
        float o = __shfl_xor_sync(0xffffffffu, s, 1);
        if (!half) ssig[p] = expf(s + o + __ldg(bd)) * sins[p];
    }
    __syncthreads();  // (3) in16/ssig visible

    // ---- c1: hc = relu([feat, ynm] @ Wc1 + bc1); ynm folded into init ----
    ull acc2[4][8];
    {
        float y0 = 0.f, y1 = 0.f, y2 = 0.f, y3 = 0.f;
#pragma unroll
        for (int j = 0; j < 16; j++) {
            float s = synm[j];
            const float* wr = Wc1 + (16 + j) * HID + cb;
            y0 = fmaf(s, __ldg(wr + 0), y0);
            y1 = fmaf(s, __ldg(wr + 1), y1);
            y2 = fmaf(s, __ldg(wr + 2), y2);
            y3 = fmaf(s, __ldg(wr + 3), y3);
        }
#pragma unroll
        for (int i = 0; i < 8; i++) {
            acc2[0][i] = pack2(y0, y0);
            acc2[1][i] = pack2(y1, y1);
            acc2[2][i] = pack2(y2, y2);
            acc2[3][i] = pack2(y3, y3);
        }
    }
    gemm_chunk<16>(Wc1, in16, cb, pb, acc2);
    __syncthreads();  // (4) all reads of bufA(h2) done before overwrite
    write_tile(bufA, bc1, cb, pb, acc2);  // hcT -> bufA
    __syncthreads();  // (5) hc visible

    // ---- c2: color = sigmoid(hc @ Wc2 + bc2), split-k all threads ----
    {
        int p = tid >> 1, half = tid & 1;
        int kb = half * 64;
        float a0 = 0.f, a1 = 0.f, a2 = 0.f;
#pragma unroll 4
        for (int k = 0; k < 64; k++) {
            float hv = bufA[(kb + k) * STR + p];
            const float* wr = wsm + 640 + (kb + k) * 3;
            a0 = fmaf(hv, wr[0], a0);
            a1 = fmaf(hv, wr[1], a1);
            a2 = fmaf(hv, wr[2], a2);
        }
        a0 += __shfl_xor_sync(0xffffffffu, a0, 1);
        a1 += __shfl_xor_sync(0xffffffffu, a1, 1);
        a2 += __shfl_xor_sync(0xffffffffu, a2, 1);
        if (!half) {
            sc0[p] = 1.f / (1.f + expf(-(a0 + __ldg(bc2 + 0))));
            sc1[p] = 1.f / (1.f + expf(-(a1 + __ldg(bc2 + 1))));
            sc2[p] = 1.f / (1.f + expf(-(a2 + __ldg(bc2 + 2))));
        }
    }
    __syncthreads();  // (6)

    // ---- integration ----
    const int wrp = tid >> 5;
    float tau = 0.f, tcur = 0.f, sc = 0.f;
    if (wrp < 2) {
        tcur = sts[tid];
        float tnext = (tid < 63) ? sts[tid + 1] : (tf + 1.0f);  // BOOSTER = 1.0
        tau = ssig[tid] * (tnext - tcur) * dnorm;
        sc = tau;
#pragma unroll
        for (int off = 1; off < 32; off <<= 1) {
            float u = __shfl_up_sync(0xffffffffu, sc, off);
            if (lane >= off) sc += u;
        }
        if (wrp == 0 && lane == 31) sred[15] = sc;
    }
    __syncthreads();  // (7)
    if (wrp < 2) {
        if (wrp == 1) sc += sred[15];
        float excl = sc - tau;
        float wgt = expf(-excl) * (1.f - expf(-tau));
        float v0 = wgt * sc0[tid];
        float v1 = wgt * sc1[tid];
        float v2 = wgt * sc2[tid];
        float v3 = wgt;
        float v4 = wgt * tcur;
#pragma unroll
        for (int off = 16; off >= 1; off >>= 1) {
            v0 += __shfl_xor_sync(0xffffffffu, v0, off);
            v1 += __shfl_xor_sync(0xffffffffu, v1, off);
            v2 += __shfl_xor_sync(0xffffffffu, v2, off);
            v3 += __shfl_xor_sync(0xffffffffu, v3, off);
            v4 += __shfl_xor_sync(0xffffffffu, v4, off);
        }
        if (lane == 0) {
            sred[wrp * 5 + 0] = v0;
            sred[wrp * 5 + 1] = v1;
            sred[wrp * 5 + 2] = v2;
            sred[wrp * 5 + 3] = v3;
            sred[wrp * 5 + 4] = v4;
        }
    }
    __syncthreads();  // (8)
    if (tid < 5) {
        float am = active ? 1.f : 0.f;
        out[ray * 5 + tid] = (sred[tid] + sred[5 + tid]) * am;
    }
}

extern "C" void kernel_launch(void* const* d_in, const int* in_sizes, int n_in,
                              void* d_out, int out_size) {
    const float* rays_o = (const float*)d_in[0];
    const float* rays_d = (const float*)d_in[1];
    const float* aabb   = (const float*)d_in[2];
    const float* W1  = (const float*)d_in[3];
    const float* b1  = (const float*)d_in[4];
    const float* W2  = (const float*)d_in[5];
    const float* b2  = (const float*)d_in[6];
    const float* Wd  = (const float*)d_in[7];
    const float* bd  = (const float*)d_in[8];
    const float* Wf  = (const float*)d_in[9];
    const float* bf  = (const float*)d_in[10];
    const float* Wc1 = (const float*)d_in[11];
    const float* bc1 = (const float*)d_in[12];
    const float* Wc2 = (const float*)d_in[13];
    const float* bc2 = (const float*)d_in[14];
    float* out = (float*)d_out;

    int n_rays = in_sizes[0] / 3;
    prep_w2<<<128, 32>>>(W2);
    size_t smem = 11552 * sizeof(float);  // 46208 B -> 3 blocks/SM (could be 4)
    cudaFuncSetAttribute(radiance_kernel, cudaFuncAttributeMaxDynamicSharedMemorySize,
                         (int)smem);
    radiance_kernel<<<n_rays, 128, smem>>>(rays_o, rays_d, aabb, W1, b1, W2, b2, Wd, bd,
                                           Wf, bf, Wc1, bc1, Wc2, bc2, out);
}